// round 4
// baseline (speedup 1.0000x reference)
#include <cuda_runtime.h>
#include <cuda_bf16.h>
#include <cfloat>
#include <math.h>

// Problem constants
#define BB 64
#define NN 2000
#define DD 128
#define HH 8
#define DHH 16
#define BEAM 16

// Scratch (no cudaMalloc allowed)
__device__ float g_kvl[(size_t)BB * NN * 384];            // ~196.6 MB
__device__ float g_fixed[BB * DD];                        // fixed context [B, D]
__device__ unsigned char g_mask[(size_t)BB * BEAM * NN];  // normalized mask
__device__ int g_isbool;

// ---------------------------------------------------------------------------
// Mask dtype detection: int32 {0,1} words have zero bytes at i%4 != 0.
// Scan only the first 1 MB of bytes (in-bounds under both encodings).
// ---------------------------------------------------------------------------
__global__ __launch_bounds__(256) void detect_mask_kernel(const unsigned char* __restrict__ m) {
  __shared__ int cnt;
  if (threadIdx.x == 0) cnt = 0;
  __syncthreads();
  int local = 0;
  for (int i = threadIdx.x; i < (1 << 20); i += 256)
    if ((i & 3) && m[i]) local = 1;
  if (local) atomicOr(&cnt, 1);
  __syncthreads();
  if (threadIdx.x == 0) g_isbool = cnt;
}

__global__ __launch_bounds__(256) void convert_mask_kernel(const unsigned char* __restrict__ m) {
  int i = blockIdx.x * 256 + threadIdx.x;
  if (i >= BB * BEAM * NN) return;
  if (g_isbool) g_mask[i] = (m[i] != 0);
  else g_mask[i] = (((const int*)m)[i] != 0);
}

// ---------------------------------------------------------------------------
// Kernel 1: fixed_ctx[b,:] = mean_n(emb[b,n,:]) @ W_fixed
// ---------------------------------------------------------------------------
__global__ __launch_bounds__(512) void fixed_ctx_kernel(
    const float* __restrict__ emb, const float* __restrict__ W_fixed) {
  int b = blockIdx.x;
  __shared__ float part[4][DD];
  __shared__ float meanv[DD];
  int d = threadIdx.x & 127;
  int c = threadIdx.x >> 7;  // 0..3
  float s = 0.f;
  for (int n = c; n < NN; n += 4) s += emb[((size_t)b * NN + n) * DD + d];
  part[c][d] = s;
  __syncthreads();
  if (c == 0) meanv[d] = (part[0][d] + part[1][d] + part[2][d] + part[3][d]) * (1.0f / (float)NN);
  __syncthreads();
  if (c == 0) {
    float a = 0.f;
#pragma unroll 8
    for (int k = 0; k < DD; k++) a = fmaf(meanv[k], W_fixed[k * DD + d], a);
    g_fixed[b * DD + d] = a;
  }
}

// ---------------------------------------------------------------------------
// Kernel 2: kvl = emb(flattened [128000,128]) @ W_node [128,384]
// Tile 128x128, BK=32, 8x8 microtile, 256 threads.
// ---------------------------------------------------------------------------
__global__ __launch_bounds__(256) void kvl_gemm(
    const float* __restrict__ A, const float* __restrict__ W) {
  __shared__ float As[32][132];  // As[k][m]
  __shared__ float Bs[32][132];  // Bs[k][n]
  const int m0 = blockIdx.y * 128;
  const int n0 = blockIdx.x * 128;
  const int tid = threadIdx.x;
  const int tx = tid & 15;
  const int ty = tid >> 4;
  const int lr = tid >> 3;
  const int lc = (tid & 7) * 4;
  const int wr = tid >> 5;
  const int wc = (tid & 31) * 4;
  float acc[8][8];
#pragma unroll
  for (int i = 0; i < 8; i++)
#pragma unroll
    for (int j = 0; j < 8; j++) acc[i][j] = 0.f;

  for (int kb = 0; kb < 128; kb += 32) {
#pragma unroll
    for (int p = 0; p < 4; p++) {
      int row = lr + 32 * p;
      float4 v = *(const float4*)&A[(size_t)(m0 + row) * 128 + kb + lc];
      As[lc + 0][row] = v.x;
      As[lc + 1][row] = v.y;
      As[lc + 2][row] = v.z;
      As[lc + 3][row] = v.w;
    }
#pragma unroll
    for (int p = 0; p < 4; p++) {
      int kr = wr + 8 * p;
      float4 v = *(const float4*)&W[(size_t)(kb + kr) * 384 + n0 + wc];
      *(float4*)&Bs[kr][wc] = v;
    }
    __syncthreads();
#pragma unroll 8
    for (int k = 0; k < 32; k++) {
      float a[8], bf[8];
      *(float4*)&a[0] = *(const float4*)&As[k][ty * 8];
      *(float4*)&a[4] = *(const float4*)&As[k][ty * 8 + 4];
      *(float4*)&bf[0] = *(const float4*)&Bs[k][tx * 8];
      *(float4*)&bf[4] = *(const float4*)&Bs[k][tx * 8 + 4];
#pragma unroll
      for (int i = 0; i < 8; i++)
#pragma unroll
        for (int j = 0; j < 8; j++) acc[i][j] = fmaf(a[i], bf[j], acc[i][j]);
    }
    __syncthreads();
  }
#pragma unroll
  for (int i = 0; i < 8; i++) {
    size_t m = (size_t)m0 + ty * 8 + i;
#pragma unroll
    for (int j = 0; j < 8; j += 4) {
      *(float4*)&g_kvl[m * 384 + n0 + tx * 8 + j] =
          make_float4(acc[i][j], acc[i][j + 1], acc[i][j + 2], acc[i][j + 3]);
    }
  }
}

// ---------------------------------------------------------------------------
// Kernel 3: per (b, beam) fused attention / logits / log_softmax / top3
// Output (float32): [log_p (B*BEAM*N)] [top_v (B*BEAM*3)] [top_i (B*BEAM*3)]
// ---------------------------------------------------------------------------
__global__ __launch_bounds__(256) void attn_kernel(
    const float* __restrict__ emb, const float* __restrict__ W_step,
    const float* __restrict__ W_out, const int* __restrict__ seq,
    float* __restrict__ out) {
  const int bm = blockIdx.x;
  const int b = bm >> 4;
  const int tid = threadIdx.x;

  __shared__ float qs[DD], ef[DD], el[DD], heads[DD], glim[DD];
  __shared__ float logits[NN];
  __shared__ float red[256];
  __shared__ float stv[256][3];
  __shared__ int sti[256][3];

  const float* __restrict__ base = g_kvl + (size_t)b * NN * 384;
  const unsigned char* __restrict__ mrow = g_mask + (size_t)bm * NN;

  // --- query build ---
  int fidx = seq[bm * 2];
  int lidx = seq[bm * 2 + 1];
  if (tid < DD) {
    ef[tid] = emb[((size_t)b * NN + fidx) * DD + tid];
    el[tid] = emb[((size_t)b * NN + lidx) * DD + tid];
  }
  __syncthreads();
  if (tid < DD) {
    float a = g_fixed[b * DD + tid];
#pragma unroll 8
    for (int k = 0; k < DD; k++) a = fmaf(ef[k], W_step[k * DD + tid], a);
#pragma unroll 8
    for (int k = 0; k < DD; k++) a = fmaf(el[k], W_step[(DD + k) * DD + tid], a);
    qs[tid] = a;
  }
  __syncthreads();

  // --- pass 1: glimpse attention, warp w handles head h=w ---
  {
    const int h = tid >> 5;
    const int lane = tid & 31;
    float qr[DHH];
#pragma unroll
    for (int t = 0; t < DHH; t++) qr[t] = qs[h * DHH + t];
    float mrun = -INFINITY, srun = 0.f;
    float acc[DHH];
#pragma unroll
    for (int t = 0; t < DHH; t++) acc[t] = 0.f;

    for (int n = lane; n < NN; n += 32) {
      if (mrow[n]) continue;
      const float* row = base + (size_t)n * 384;
      float4 k0 = *(const float4*)(row + h * DHH);
      float4 k1 = *(const float4*)(row + h * DHH + 4);
      float4 k2 = *(const float4*)(row + h * DHH + 8);
      float4 k3 = *(const float4*)(row + h * DHH + 12);
      float s = 0.f;
      s = fmaf(qr[0], k0.x, s);  s = fmaf(qr[1], k0.y, s);
      s = fmaf(qr[2], k0.z, s);  s = fmaf(qr[3], k0.w, s);
      s = fmaf(qr[4], k1.x, s);  s = fmaf(qr[5], k1.y, s);
      s = fmaf(qr[6], k1.z, s);  s = fmaf(qr[7], k1.w, s);
      s = fmaf(qr[8], k2.x, s);  s = fmaf(qr[9], k2.y, s);
      s = fmaf(qr[10], k2.z, s); s = fmaf(qr[11], k2.w, s);
      s = fmaf(qr[12], k3.x, s); s = fmaf(qr[13], k3.y, s);
      s = fmaf(qr[14], k3.z, s); s = fmaf(qr[15], k3.w, s);
      s *= 0.25f;  // 1/sqrt(dh)

      float mn = fmaxf(mrun, s);
      float sc = (mrun == mn) ? 1.f : __expf(mrun - mn);
      float p = __expf(s - mn);
      srun = srun * sc + p;
      const float* vrow = row + 128 + h * DHH;
      float4 v0 = *(const float4*)(vrow);
      float4 v1 = *(const float4*)(vrow + 4);
      float4 v2 = *(const float4*)(vrow + 8);
      float4 v3 = *(const float4*)(vrow + 12);
      float vv[16] = {v0.x, v0.y, v0.z, v0.w, v1.x, v1.y, v1.z, v1.w,
                      v2.x, v2.y, v2.z, v2.w, v3.x, v3.y, v3.z, v3.w};
#pragma unroll
      for (int t = 0; t < DHH; t++) acc[t] = acc[t] * sc + p * vv[t];
      mrun = mn;
    }
#pragma unroll
    for (int off = 16; off > 0; off >>= 1) {
      float mo = __shfl_down_sync(0xffffffffu, mrun, off);
      float so = __shfl_down_sync(0xffffffffu, srun, off);
      float mn = fmaxf(mrun, mo);
      float s1 = (mrun == mn) ? 1.f : __expf(mrun - mn);
      float s2 = (mo == mn) ? 1.f : __expf(mo - mn);
      srun = srun * s1 + so * s2;
#pragma unroll
      for (int t = 0; t < DHH; t++) {
        float ao = __shfl_down_sync(0xffffffffu, acc[t], off);
        acc[t] = acc[t] * s1 + ao * s2;
      }
      mrun = mn;
    }
    if (lane == 0) {
      float inv = 1.f / srun;
#pragma unroll
      for (int t = 0; t < DHH; t++) heads[h * DHH + t] = acc[t] * inv;
    }
  }
  __syncthreads();

  // --- glimpse = heads @ W_out ---
  if (tid < DD) {
    float a = 0.f;
#pragma unroll 8
    for (int k = 0; k < DD; k++) a = fmaf(heads[k], W_out[k * DD + tid], a);
    glim[tid] = a;
  }
  __syncthreads();

  // --- pass 2: logits vs lk, tanh clip, mask, log_softmax, top3 ---
  const float invsq = 0.08838834764831845f;  // 1/sqrt(128)
  float tv0 = -INFINITY, tv1 = -INFINITY, tv2 = -INFINITY;
  int ti0 = 0, ti1 = 0, ti2 = 0;
  float lmax = -INFINITY;
  for (int n = tid; n < NN; n += 256) {
    const float* row = base + (size_t)n * 384 + 256;
    float s = 0.f;
#pragma unroll
    for (int kk = 0; kk < 32; kk++) {
      float4 g = *(const float4*)&glim[kk * 4];
      float4 x = *(const float4*)(row + kk * 4);
      s = fmaf(g.x, x.x, s);
      s = fmaf(g.y, x.y, s);
      s = fmaf(g.z, x.z, s);
      s = fmaf(g.w, x.w, s);
    }
    float v = 10.f * tanhf(s * invsq);
    if (mrow[n]) v = -FLT_MAX;
    logits[n] = v;
    lmax = fmaxf(lmax, v);
    if (v > tv0) { tv2 = tv1; ti2 = ti1; tv1 = tv0; ti1 = ti0; tv0 = v; ti0 = n; }
    else if (v > tv1) { tv2 = tv1; ti2 = ti1; tv1 = v; ti1 = n; }
    else if (v > tv2) { tv2 = v; ti2 = n; }
  }
  stv[tid][0] = tv0; stv[tid][1] = tv1; stv[tid][2] = tv2;
  sti[tid][0] = ti0; sti[tid][1] = ti1; sti[tid][2] = ti2;
  red[tid] = lmax;
  __syncthreads();
  for (int s2 = 128; s2 > 0; s2 >>= 1) {
    if (tid < s2) red[tid] = fmaxf(red[tid], red[tid + s2]);
    __syncthreads();
  }
  lmax = red[0];
  __syncthreads();
  float lsum = 0.f;
  for (int n = tid; n < NN; n += 256) lsum += __expf(logits[n] - lmax);
  red[tid] = lsum;
  __syncthreads();
  for (int s2 = 128; s2 > 0; s2 >>= 1) {
    if (tid < s2) red[tid] += red[tid + s2];
    __syncthreads();
  }
  const float lse = lmax + __logf(red[0]);

  float* __restrict__ lp = out + (size_t)bm * NN;
  for (int n = tid; n < NN; n += 256) lp[n] = logits[n] - lse;

  if (tid == 0) {
    float bv0 = -INFINITY, bv1 = -INFINITY, bv2 = -INFINITY;
    int bi0 = 0, bi1 = 0, bi2 = 0;
    for (int t = 0; t < 256; t++) {
#pragma unroll
      for (int j = 0; j < 3; j++) {
        float v = stv[t][j];
        int i = sti[t][j];
        if (v > bv0) { bv2 = bv1; bi2 = bi1; bv1 = bv0; bi1 = bi0; bv0 = v; bi0 = i; }
        else if (v > bv1) { bv2 = bv1; bi2 = bi1; bv1 = v; bi1 = i; }
        else if (v > bv2) { bv2 = v; bi2 = i; }
      }
    }
    float* tvo = out + (size_t)BB * BEAM * NN + bm * 3;
    float* tio = out + (size_t)BB * BEAM * NN + (size_t)BB * BEAM * 3 + bm * 3;
    tvo[0] = bv0 - lse; tvo[1] = bv1 - lse; tvo[2] = bv2 - lse;
    tio[0] = (float)bi0; tio[1] = (float)bi1; tio[2] = (float)bi2;
  }
}

// ---------------------------------------------------------------------------
extern "C" void kernel_launch(void* const* d_in, const int* in_sizes, int n_in,
                              void* d_out, int out_size) {
  // Bind inputs by element count (robust to metadata ordering).
  const float* emb = nullptr;
  const float* W_node = nullptr;
  const float* W_fixed = nullptr;
  const float* W_step = nullptr;
  const float* W_out = nullptr;
  const int* seq = nullptr;
  const unsigned char* mask = nullptr;
  for (int i = 0; i < n_in; i++) {
    int sz = in_sizes[i];
    if (sz == BB * NN * DD) emb = (const float*)d_in[i];
    else if (sz == DD * 3 * DD) W_node = (const float*)d_in[i];
    else if (sz == 2 * DD * DD) W_step = (const float*)d_in[i];
    else if (sz == BB * BEAM * 2) seq = (const int*)d_in[i];
    else if (sz == BB * BEAM * NN) mask = (const unsigned char*)d_in[i];
    else if (sz == DD * DD) {
      if (!W_fixed) W_fixed = (const float*)d_in[i];
      else W_out = (const float*)d_in[i];
    }
  }
  float* out = (float*)d_out;

  detect_mask_kernel<<<1, 256>>>(mask);
  convert_mask_kernel<<<(BB * BEAM * NN + 255) / 256, 256>>>(mask);
  fixed_ctx_kernel<<<BB, 512>>>(emb, W_fixed);
  kvl_gemm<<<dim3(3, (BB * NN) / 128), 256>>>(emb, W_node);
  attn_kernel<<<BB * BEAM, 256>>>(emb, W_step, W_out, seq, out);
}

// round 5
// speedup vs baseline: 1.4055x; 1.4055x over previous
#include <cuda_runtime.h>
#include <cuda_bf16.h>
#include <cfloat>
#include <math.h>

// Problem constants
#define BB 64
#define NN 2000
#define DD 128
#define HH 8
#define DHH 16
#define BEAM 16

// Scratch (no cudaMalloc allowed)
// Feature-major kvl: g_kt[b][f][n], f in 0..383 (gk 0..127, gv 128..255, lk 256..383)
// +64 floats padding so half-warp tail overreads stay in-bounds.
__device__ float g_kt[(size_t)BB * 384 * NN + 64];        // ~196.6 MB
__device__ float g_fixed[BB * DD];                        // fixed context [B, D]
__device__ unsigned char g_mask[(size_t)BB * BEAM * NN];  // normalized mask
__device__ int g_isbool;

// ---------------------------------------------------------------------------
// Mask dtype detection: int32 {0,1} words have zero bytes at i%4 != 0.
// Scan first 1 MB (in-bounds under both encodings), 64 blocks.
// ---------------------------------------------------------------------------
__global__ __launch_bounds__(256) void detect_mask_kernel(const unsigned char* __restrict__ m) {
  int base = blockIdx.x * (1 << 14);
  int local = 0;
  for (int i = threadIdx.x; i < (1 << 14); i += 256) {
    int idx = base + i;
    if ((idx & 3) && m[idx]) local = 1;
  }
  if (__syncthreads_or(local)) {
    if (threadIdx.x == 0) g_isbool = 1;
  }
}

__global__ __launch_bounds__(256) void convert_mask_kernel(const unsigned char* __restrict__ m) {
  int i = blockIdx.x * 256 + threadIdx.x;
  if (i >= BB * BEAM * NN) return;
  if (g_isbool) g_mask[i] = (m[i] != 0);
  else g_mask[i] = (((const int*)m)[i] != 0);
}

__global__ void zero_isbool_kernel() { g_isbool = 0; }

// ---------------------------------------------------------------------------
// Kernel 1: fixed_ctx[b,:] = mean_n(emb[b,n,:]) @ W_fixed
// ---------------------------------------------------------------------------
__global__ __launch_bounds__(512) void fixed_ctx_kernel(
    const float* __restrict__ emb, const float* __restrict__ W_fixed) {
  int b = blockIdx.x;
  __shared__ float part[4][DD];
  __shared__ float meanv[DD];
  int d = threadIdx.x & 127;
  int c = threadIdx.x >> 7;  // 0..3
  float s = 0.f;
  for (int n = c; n < NN; n += 4) s += emb[((size_t)b * NN + n) * DD + d];
  part[c][d] = s;
  __syncthreads();
  if (c == 0) meanv[d] = (part[0][d] + part[1][d] + part[2][d] + part[3][d]) * (1.0f / (float)NN);
  __syncthreads();
  if (c == 0) {
    float a = 0.f;
#pragma unroll 8
    for (int k = 0; k < DD; k++) a = fmaf(meanv[k], W_fixed[k * DD + d], a);
    g_fixed[b * DD + d] = a;
  }
}

// ---------------------------------------------------------------------------
// Kernel 2: kvl = emb(flattened [128000,128]) @ W_node [128,384],
// written FEATURE-MAJOR to g_kt[b][f][n] via smem transpose epilogue.
// Tile 128(m) x 128(f), BK=32, 8x8 microtile, 256 threads. grid (3, 1000).
// ---------------------------------------------------------------------------
__global__ __launch_bounds__(256) void kvl_gemm(
    const float* __restrict__ A, const float* __restrict__ W) {
  __shared__ float As[32][132];  // As[k][m] in mainloop; reused as transpose buf
  __shared__ float Bs[32][132];  // Bs[k][n]
  const int m0 = blockIdx.y * 128;
  const int n0 = blockIdx.x * 128;
  const int tid = threadIdx.x;
  const int tx = tid & 15;
  const int ty = tid >> 4;
  const int lr = tid >> 3;
  const int lc = (tid & 7) * 4;
  const int wr = tid >> 5;
  const int wc = (tid & 31) * 4;
  float acc[8][8];
#pragma unroll
  for (int i = 0; i < 8; i++)
#pragma unroll
    for (int j = 0; j < 8; j++) acc[i][j] = 0.f;

  for (int kb = 0; kb < 128; kb += 32) {
#pragma unroll
    for (int p = 0; p < 4; p++) {
      int row = lr + 32 * p;
      float4 v = *(const float4*)&A[(size_t)(m0 + row) * 128 + kb + lc];
      As[lc + 0][row] = v.x;
      As[lc + 1][row] = v.y;
      As[lc + 2][row] = v.z;
      As[lc + 3][row] = v.w;
    }
#pragma unroll
    for (int p = 0; p < 4; p++) {
      int kr = wr + 8 * p;
      float4 v = *(const float4*)&W[(size_t)(kb + kr) * 384 + n0 + wc];
      *(float4*)&Bs[kr][wc] = v;
    }
    __syncthreads();
#pragma unroll 8
    for (int k = 0; k < 32; k++) {
      float a[8], bf[8];
      *(float4*)&a[0] = *(const float4*)&As[k][ty * 8];
      *(float4*)&a[4] = *(const float4*)&As[k][ty * 8 + 4];
      *(float4*)&bf[0] = *(const float4*)&Bs[k][tx * 8];
      *(float4*)&bf[4] = *(const float4*)&Bs[k][tx * 8 + 4];
#pragma unroll
      for (int i = 0; i < 8; i++)
#pragma unroll
        for (int j = 0; j < 8; j++) acc[i][j] = fmaf(a[i], bf[j], acc[i][j]);
    }
    __syncthreads();
  }

  // --- transpose epilogue: 4 chunks of 32 feature-rows through As ---
#pragma unroll 1
  for (int c = 0; c < 4; c++) {
    if ((tx >> 2) == c) {  // tx in [4c, 4c+4): features tx*8+j in [32c, 32c+32)
#pragma unroll
      for (int i = 0; i < 8; i++)
#pragma unroll
        for (int j = 0; j < 8; j++)
          As[(tx - 4 * c) * 8 + j][ty * 8 + i] = acc[i][j];
    }
    __syncthreads();
#pragma unroll
    for (int j4 = 0; j4 < 4; j4++) {
      int fr = (tid >> 5) + 8 * j4;     // 0..31
      int mloc = (tid & 31) * 4;        // 0..124
      int gf = n0 + 32 * c + fr;        // global feature 0..383
#pragma unroll
      for (int e = 0; e < 4; e++) {
        int m = m0 + mloc + e;
        int b = m / NN;
        int n = m - b * NN;
        g_kt[((size_t)b * 384 + gf) * NN + n] = As[fr][mloc + e];
      }
    }
    __syncthreads();
  }
}

// ---------------------------------------------------------------------------
// Kernel 3: per (b, beam) fused attention / logits / log_softmax / top3
// reading feature-major g_kt (coalesced node-contiguous loads).
// Output (float32): [log_p (B*BEAM*N)] [top_v (B*BEAM*3)] [top_i (B*BEAM*3)]
// ---------------------------------------------------------------------------
__global__ __launch_bounds__(256) void attn_kernel(
    const float* __restrict__ emb, const float* __restrict__ W_step,
    const float* __restrict__ W_out, const int* __restrict__ seq,
    float* __restrict__ out) {
  const int bm = blockIdx.x;
  const int b = bm >> 4;
  const int tid = threadIdx.x;

  __shared__ float qs[DD], ef[DD], el[DD], heads[DD], glim[DD];
  __shared__ float logits[NN];
  __shared__ float red[256];
  __shared__ float stv[256][3];
  __shared__ int sti[256][3];

  const unsigned char* __restrict__ mrow = g_mask + (size_t)bm * NN;

  // --- query build ---
  int fidx = seq[bm * 2];
  int lidx = seq[bm * 2 + 1];
  if (tid < DD) {
    ef[tid] = emb[((size_t)b * NN + fidx) * DD + tid];
    el[tid] = emb[((size_t)b * NN + lidx) * DD + tid];
  }
  __syncthreads();
  if (tid < DD) {
    float a = g_fixed[b * DD + tid];
#pragma unroll 8
    for (int k = 0; k < DD; k++) a = fmaf(ef[k], W_step[k * DD + tid], a);
#pragma unroll 8
    for (int k = 0; k < DD; k++) a = fmaf(el[k], W_step[(DD + k) * DD + tid], a);
    qs[tid] = a;
  }
  __syncthreads();

  // --- pass 1: glimpse attention, warp w handles head h=w ---
  {
    const int h = tid >> 5;
    const int lane = tid & 31;
    const float* __restrict__ gk = g_kt + ((size_t)b * 384 + h * DHH) * NN;
    const float* __restrict__ gv = g_kt + ((size_t)b * 384 + 128 + h * DHH) * NN;
    float qr[DHH];
#pragma unroll
    for (int t = 0; t < DHH; t++) qr[t] = qs[h * DHH + t];
    float mrun = -1e30f, srun = 0.f;
    float acc[DHH];
#pragma unroll
    for (int t = 0; t < DHH; t++) acc[t] = 0.f;

#pragma unroll 1
    for (int k = 0; k < 63; k++) {
      const int n = lane + 32 * k;
      // loads are unconditional (g_kt padded); mask byte is guarded.
      const unsigned char mb = (n < NN) ? mrow[n] : (unsigned char)1;
      float s = 0.f;
#pragma unroll
      for (int t = 0; t < DHH; t++) s = fmaf(qr[t], gk[t * NN + n], s);
      s = mb ? -1e30f : s * 0.25f;  // 1/sqrt(dh); masked -> huge negative (exp underflows to 0)
      float vv[DHH];
#pragma unroll
      for (int t = 0; t < DHH; t++) vv[t] = gv[t * NN + n];
      float mn = fmaxf(mrun, s);
      float sc = __expf(mrun - mn);
      float p = __expf(s - mn);
      srun = srun * sc + p;
#pragma unroll
      for (int t = 0; t < DHH; t++) acc[t] = acc[t] * sc + p * vv[t];
      mrun = mn;
    }
    // warp reduce (combine online-softmax states)
#pragma unroll
    for (int off = 16; off > 0; off >>= 1) {
      float mo = __shfl_down_sync(0xffffffffu, mrun, off);
      float so = __shfl_down_sync(0xffffffffu, srun, off);
      float mn = fmaxf(mrun, mo);
      float s1 = __expf(mrun - mn);
      float s2 = __expf(mo - mn);
      srun = srun * s1 + so * s2;
#pragma unroll
      for (int t = 0; t < DHH; t++) {
        float ao = __shfl_down_sync(0xffffffffu, acc[t], off);
        acc[t] = acc[t] * s1 + ao * s2;
      }
      mrun = mn;
    }
    if (lane == 0) {
      float inv = 1.f / srun;
#pragma unroll
      for (int t = 0; t < DHH; t++) heads[h * DHH + t] = acc[t] * inv;
    }
  }
  __syncthreads();

  // --- glimpse = heads @ W_out ---
  if (tid < DD) {
    float a = 0.f;
#pragma unroll 8
    for (int k = 0; k < DD; k++) a = fmaf(heads[k], W_out[k * DD + tid], a);
    glim[tid] = a;
  }
  __syncthreads();

  // --- pass 2: logits vs lk (feature-major), tanh clip, mask, log_softmax, top3 ---
  const float* __restrict__ lk = g_kt + ((size_t)b * 384 + 256) * NN;
  const float invsq = 0.08838834764831845f;  // 1/sqrt(128)
  float tv0 = -INFINITY, tv1 = -INFINITY, tv2 = -INFINITY;
  int ti0 = 0, ti1 = 0, ti2 = 0;
  float lmax = -INFINITY;
#pragma unroll 1
  for (int k = 0; k < 8; k++) {
    const int n = tid + 256 * k;
    if (n >= NN) break;
    float s = 0.f;
#pragma unroll
    for (int f = 0; f < DD; f++) s = fmaf(glim[f], lk[(size_t)f * NN + n], s);
    float v = 10.f * tanhf(s * invsq);
    if (mrow[n]) v = -FLT_MAX;
    logits[n] = v;
    lmax = fmaxf(lmax, v);
    if (v > tv0) { tv2 = tv1; ti2 = ti1; tv1 = tv0; ti1 = ti0; tv0 = v; ti0 = n; }
    else if (v > tv1) { tv2 = tv1; ti2 = ti1; tv1 = v; ti1 = n; }
    else if (v > tv2) { tv2 = v; ti2 = n; }
  }
  stv[tid][0] = tv0; stv[tid][1] = tv1; stv[tid][2] = tv2;
  sti[tid][0] = ti0; sti[tid][1] = ti1; sti[tid][2] = ti2;
  red[tid] = lmax;
  __syncthreads();
  for (int s2 = 128; s2 > 0; s2 >>= 1) {
    if (tid < s2) red[tid] = fmaxf(red[tid], red[tid + s2]);
    __syncthreads();
  }
  lmax = red[0];
  __syncthreads();
  float lsum = 0.f;
  for (int n = tid; n < NN; n += 256) lsum += __expf(logits[n] - lmax);
  red[tid] = lsum;
  __syncthreads();
  for (int s2 = 128; s2 > 0; s2 >>= 1) {
    if (tid < s2) red[tid] += red[tid + s2];
    __syncthreads();
  }
  const float lse = lmax + __logf(red[0]);

  float* __restrict__ lp = out + (size_t)bm * NN;
  for (int n = tid; n < NN; n += 256) lp[n] = logits[n] - lse;

  // --- parallel tree merge of per-thread top-3 triples ---
  for (int s2 = 128; s2 > 0; s2 >>= 1) {
    if (tid < s2) {
      float a0 = stv[tid][0], a1 = stv[tid][1], a2 = stv[tid][2];
      int i0 = sti[tid][0], i1 = sti[tid][1], i2 = sti[tid][2];
#pragma unroll
      for (int j = 0; j < 3; j++) {
        float v = stv[tid + s2][j];
        int ii = sti[tid + s2][j];
        if (v > a0) { a2 = a1; i2 = i1; a1 = a0; i1 = i0; a0 = v; i0 = ii; }
        else if (v > a1) { a2 = a1; i2 = i1; a1 = v; i1 = ii; }
        else if (v > a2) { a2 = v; i2 = ii; }
      }
      stv[tid][0] = a0; stv[tid][1] = a1; stv[tid][2] = a2;
      sti[tid][0] = i0; sti[tid][1] = i1; sti[tid][2] = i2;
    }
    __syncthreads();
  }
  if (tid == 0) {
    float* tvo = out + (size_t)BB * BEAM * NN + bm * 3;
    float* tio = out + (size_t)BB * BEAM * NN + (size_t)BB * BEAM * 3 + bm * 3;
    tvo[0] = stv[0][0] - lse; tvo[1] = stv[0][1] - lse; tvo[2] = stv[0][2] - lse;
    tio[0] = (float)sti[0][0]; tio[1] = (float)sti[0][1]; tio[2] = (float)sti[0][2];
  }
}

// ---------------------------------------------------------------------------
extern "C" void kernel_launch(void* const* d_in, const int* in_sizes, int n_in,
                              void* d_out, int out_size) {
  // Bind inputs by element count (robust to metadata ordering).
  const float* emb = nullptr;
  const float* W_node = nullptr;
  const float* W_fixed = nullptr;
  const float* W_step = nullptr;
  const float* W_out = nullptr;
  const int* seq = nullptr;
  const unsigned char* mask = nullptr;
  for (int i = 0; i < n_in; i++) {
    int sz = in_sizes[i];
    if (sz == BB * NN * DD) emb = (const float*)d_in[i];
    else if (sz == DD * 3 * DD) W_node = (const float*)d_in[i];
    else if (sz == 2 * DD * DD) W_step = (const float*)d_in[i];
    else if (sz == BB * BEAM * 2) seq = (const int*)d_in[i];
    else if (sz == BB * BEAM * NN) mask = (const unsigned char*)d_in[i];
    else if (sz == DD * DD) {
      if (!W_fixed) W_fixed = (const float*)d_in[i];
      else W_out = (const float*)d_in[i];
    }
  }
  float* out = (float*)d_out;

  zero_isbool_kernel<<<1, 1>>>();
  detect_mask_kernel<<<64, 256>>>(mask);
  convert_mask_kernel<<<(BB * BEAM * NN + 255) / 256, 256>>>(mask);
  fixed_ctx_kernel<<<BB, 512>>>(emb, W_fixed);
  kvl_gemm<<<dim3(3, (BB * NN) / 128), 256>>>(emb, W_node);
  attn_kernel<<<BB * BEAM, 256>>>(emb, W_step, W_out, seq, out);
}

// round 6
// speedup vs baseline: 2.4327x; 1.7308x over previous
#include <cuda_runtime.h>
#include <cuda_bf16.h>
#include <cfloat>
#include <math.h>

// Problem constants
#define BB 64
#define NN 2000
#define DD 128
#define HH 8
#define DHH 16
#define BEAM 16
#define NCHUNK 8
#define CHN 250   // nodes per chunk (8*250 = 2000)

// Scratch (no cudaMalloc allowed)
// Feature-major kvl: g_kt[b][f][n], f 0..383 (gk 0..127, gv 128..255, lk 256..383)
__device__ float g_kt[(size_t)BB * 384 * NN + 64];        // ~196.6 MB
__device__ unsigned char g_mask[(size_t)BB * BEAM * NN];  // normalized mask
__device__ int g_isbool;
__device__ float g_fpart[BB * NCHUNK * DD];               // mean partial sums
__device__ float g_q[BB * BEAM * DD];                     // queries
__device__ float g_pm[BB * NCHUNK * HH * BEAM];           // partial softmax max
__device__ float g_ps[BB * NCHUNK * HH * BEAM];           // partial softmax sum
__device__ float g_pacc[BB * NCHUNK * HH * BEAM * DHH];   // partial weighted V
__device__ float g_glim[BB * BEAM * DD];                  // glimpse vectors

// fma-pipe exp for x <= 0 (clamped); rel err ~3e-8. No MUFU.
__device__ __forceinline__ float fexp(float x) {
  x = fmaxf(x, -80.f);
  float y = x * 1.4426950408889634f;
  float r = y + 12582912.f;          // round-to-nearest int (|y| < 2^22)
  float k = r - 12582912.f;
  float f = y - k;
  float p = 1.5403530393381609e-4f;
  p = fmaf(p, f, 1.3333558146428443e-3f);
  p = fmaf(p, f, 9.6181291976353993e-3f);
  p = fmaf(p, f, 5.5504108664821580e-2f);
  p = fmaf(p, f, 2.4022650695910071e-1f);
  p = fmaf(p, f, 6.9314718055994531e-1f);
  p = fmaf(p, f, 1.0f);
  int e = (int)k;                    // e in [-116, 0]
  return p * __int_as_float((e + 127) << 23);
}

// ---------------------------------------------------------------------------
// Mask dtype detection + normalization (unchanged; passed rounds 4-5)
// ---------------------------------------------------------------------------
__global__ void zero_isbool_kernel() { g_isbool = 0; }

__global__ __launch_bounds__(256) void detect_mask_kernel(const unsigned char* __restrict__ m) {
  int base = blockIdx.x * (1 << 14);
  int local = 0;
  for (int i = threadIdx.x; i < (1 << 14); i += 256) {
    int idx = base + i;
    if ((idx & 3) && m[idx]) local = 1;
  }
  if (__syncthreads_or(local)) {
    if (threadIdx.x == 0) g_isbool = 1;
  }
}

__global__ __launch_bounds__(256) void convert_mask_kernel(const unsigned char* __restrict__ m) {
  int i = blockIdx.x * 256 + threadIdx.x;
  if (i >= BB * BEAM * NN) return;
  if (g_isbool) g_mask[i] = (m[i] != 0);
  else g_mask[i] = (((const int*)m)[i] != 0);
}

// ---------------------------------------------------------------------------
// K1: mean partial sums: g_fpart[b][c][d] = sum_{n in chunk c} emb[b,n,d]
// grid (64, 8), 128 threads
// ---------------------------------------------------------------------------
__global__ __launch_bounds__(128) void fpart_kernel(const float* __restrict__ emb) {
  int b = blockIdx.x, c = blockIdx.y, d = threadIdx.x;
  const float* p = emb + ((size_t)b * NN + c * CHN) * DD + d;
  float s = 0.f;
#pragma unroll 5
  for (int n = 0; n < CHN; n++) s += p[n * DD];
  g_fpart[(b * NCHUNK + c) * DD + d] = s;
}

// ---------------------------------------------------------------------------
// K2: kvl = emb[128000,128] @ W_node[128,384] -> g_kt feature-major
// (unchanged from round 5)
// ---------------------------------------------------------------------------
__global__ __launch_bounds__(256) void kvl_gemm(
    const float* __restrict__ A, const float* __restrict__ W) {
  __shared__ float As[32][132];
  __shared__ float Bs[32][132];
  const int m0 = blockIdx.y * 128;
  const int n0 = blockIdx.x * 128;
  const int tid = threadIdx.x;
  const int tx = tid & 15;
  const int ty = tid >> 4;
  const int lr = tid >> 3;
  const int lc = (tid & 7) * 4;
  const int wr = tid >> 5;
  const int wc = (tid & 31) * 4;
  float acc[8][8];
#pragma unroll
  for (int i = 0; i < 8; i++)
#pragma unroll
    for (int j = 0; j < 8; j++) acc[i][j] = 0.f;

  for (int kb = 0; kb < 128; kb += 32) {
#pragma unroll
    for (int p = 0; p < 4; p++) {
      int row = lr + 32 * p;
      float4 v = *(const float4*)&A[(size_t)(m0 + row) * 128 + kb + lc];
      As[lc + 0][row] = v.x;
      As[lc + 1][row] = v.y;
      As[lc + 2][row] = v.z;
      As[lc + 3][row] = v.w;
    }
#pragma unroll
    for (int p = 0; p < 4; p++) {
      int kr = wr + 8 * p;
      float4 v = *(const float4*)&W[(size_t)(kb + kr) * 384 + n0 + wc];
      *(float4*)&Bs[kr][wc] = v;
    }
    __syncthreads();
#pragma unroll 8
    for (int k = 0; k < 32; k++) {
      float a[8], bf[8];
      *(float4*)&a[0] = *(const float4*)&As[k][ty * 8];
      *(float4*)&a[4] = *(const float4*)&As[k][ty * 8 + 4];
      *(float4*)&bf[0] = *(const float4*)&Bs[k][tx * 8];
      *(float4*)&bf[4] = *(const float4*)&Bs[k][tx * 8 + 4];
#pragma unroll
      for (int i = 0; i < 8; i++)
#pragma unroll
        for (int j = 0; j < 8; j++) acc[i][j] = fmaf(a[i], bf[j], acc[i][j]);
    }
    __syncthreads();
  }
  // transpose epilogue
#pragma unroll 1
  for (int c = 0; c < 4; c++) {
    if ((tx >> 2) == c) {
#pragma unroll
      for (int i = 0; i < 8; i++)
#pragma unroll
        for (int j = 0; j < 8; j++)
          As[(tx - 4 * c) * 8 + j][ty * 8 + i] = acc[i][j];
    }
    __syncthreads();
#pragma unroll
    for (int j4 = 0; j4 < 4; j4++) {
      int fr = (tid >> 5) + 8 * j4;
      int mloc = (tid & 31) * 4;
      int gf = n0 + 32 * c + fr;
#pragma unroll
      for (int e = 0; e < 4; e++) {
        int m = m0 + mloc + e;
        int b = m / NN;
        int n = m - b * NN;
        g_kt[((size_t)b * 384 + gf) * NN + n] = As[fr][mloc + e];
      }
    }
    __syncthreads();
  }
}

// ---------------------------------------------------------------------------
// K3: query build: g_q[b][m][d] = fixed_ctx[b][d] + [ef;el] @ W_step
// grid 1024 (b*16+m), 128 threads
// ---------------------------------------------------------------------------
__global__ __launch_bounds__(128) void query_kernel(
    const float* __restrict__ emb, const float* __restrict__ W_fixed,
    const float* __restrict__ W_step, const int* __restrict__ seq) {
  const int bm = blockIdx.x;
  const int b = bm >> 4;
  const int d = threadIdx.x;
  __shared__ float mean[DD], ef[DD], el[DD];
  float s = 0.f;
#pragma unroll
  for (int c = 0; c < NCHUNK; c++) s += g_fpart[(b * NCHUNK + c) * DD + d];
  mean[d] = s * (1.0f / (float)NN);
  int fidx = seq[bm * 2];
  int lidx = seq[bm * 2 + 1];
  ef[d] = emb[((size_t)b * NN + fidx) * DD + d];
  el[d] = emb[((size_t)b * NN + lidx) * DD + d];
  __syncthreads();
  float a = 0.f;
#pragma unroll 8
  for (int k = 0; k < DD; k++) a = fmaf(mean[k], W_fixed[k * DD + d], a);
#pragma unroll 8
  for (int k = 0; k < DD; k++) a = fmaf(ef[k], W_step[k * DD + d], a);
#pragma unroll 8
  for (int k = 0; k < DD; k++) a = fmaf(el[k], W_step[(DD + k) * DD + d], a);
  g_q[bm * DD + d] = a;
}

// ---------------------------------------------------------------------------
// K4: beam-batched glimpse partials. grid (64 b, 8 chunks), 256 threads.
// Warp w = head h. Per group of 32 nodes:
//   phase A (lane=node): load k/v, compute raw scores for 16 beams -> smem
//   phase B (lane=(beam,tgroup)): masked online-softmax update of (m,s,acc[8])
// Writes per-(b,c,h,m) partial state.
// ---------------------------------------------------------------------------
__global__ __launch_bounds__(256) void glimpse_kernel() {
  const int b = blockIdx.x, c = blockIdx.y;
  const int n0 = c * CHN;
  const int tid = threadIdx.x;
  const int h = tid >> 5;
  const int lane = tid & 31;

  __shared__ float q_s[BEAM][DD];            // 8 KB
  __shared__ unsigned char mk[BEAM][260];    // ~4 KB (260 pad: bank-spread)
  __shared__ float s_s[HH][BEAM][33];        // 16.9 KB
  __shared__ float v_s[HH][DHH][33];         // 16.9 KB

  for (int i = tid; i < BEAM * DD; i += 256) q_s[i >> 7][i & 127] = g_q[b * BEAM * DD + i];
  for (int i = tid; i < BEAM * 256; i += 256) {
    int m = i >> 8, n = i & 255;
    mk[m][n] = (n < CHN) ? g_mask[((size_t)(b * BEAM + m)) * NN + n0 + n] : (unsigned char)1;
  }
  __syncthreads();

  const float* __restrict__ gk = g_kt + ((size_t)b * 384 + h * DHH) * NN;
  const float* __restrict__ gv = g_kt + ((size_t)b * 384 + 128 + h * DHH) * NN;

  const int mown = lane & 15;
  const int tg = lane >> 4;
  float m_run = -1e30f, s_run = 0.f;
  float acc[8];
#pragma unroll
  for (int j = 0; j < 8; j++) acc[j] = 0.f;

#pragma unroll 1
  for (int g = 0; g < 8; g++) {
    const int nl = g * 32 + lane;
    const bool valid = nl < CHN;
    const int n = n0 + nl;
    // --- phase A: lane = node ---
    float kf[DHH];
#pragma unroll
    for (int t = 0; t < DHH; t++) kf[t] = valid ? gk[(size_t)t * NN + n] : 0.f;
#pragma unroll
    for (int t = 0; t < DHH; t++) v_s[h][t][lane] = valid ? gv[(size_t)t * NN + n] : 0.f;
#pragma unroll
    for (int mi = 0; mi < BEAM; mi++) {
      const float4* qv = (const float4*)&q_s[mi][h * DHH];
      float s = 0.f;
#pragma unroll
      for (int t4 = 0; t4 < 4; t4++) {
        float4 q4 = qv[t4];
        s = fmaf(q4.x, kf[t4 * 4 + 0], s);
        s = fmaf(q4.y, kf[t4 * 4 + 1], s);
        s = fmaf(q4.z, kf[t4 * 4 + 2], s);
        s = fmaf(q4.w, kf[t4 * 4 + 3], s);
      }
      s_s[h][mi][lane] = valid ? s * 0.25f : -1e30f;
    }
    __syncwarp();
    // --- phase B: lane owns (mown, tg); both tg lanes track same (m,s) ---
    float gm = -1e30f;
#pragma unroll
    for (int j = 0; j < 32; j++) {
      float s = mk[mown][g * 32 + j] ? -1e30f : s_s[h][mown][j];
      s_s[h][mown][j] = s;  // write back masked (lanes paired by tg write same value)
      gm = fmaxf(gm, s);
    }
    float mnew = fmaxf(m_run, gm);
    float scale = fexp(m_run - mnew);
    float ssum = 0.f;
#pragma unroll
    for (int j = 0; j < 8; j++) acc[j] *= scale;
#pragma unroll
    for (int j = 0; j < 32; j++) {
      float p = fexp(s_s[h][mown][j] - mnew);
      ssum += p;
#pragma unroll
      for (int jj = 0; jj < 8; jj++) acc[jj] = fmaf(p, v_s[h][tg * 8 + jj][j], acc[jj]);
    }
    s_run = s_run * scale + ssum;
    m_run = mnew;
    __syncwarp();
  }
  const int idx = ((b * NCHUNK + c) * HH + h) * BEAM + mown;
  if (tg == 0) { g_pm[idx] = m_run; g_ps[idx] = s_run; }
#pragma unroll
  for (int j = 0; j < 8; j++) g_pacc[idx * DHH + tg * 8 + j] = acc[j];
}

// ---------------------------------------------------------------------------
// K5: reduce partials -> heads -> glimpse = heads @ W_out
// grid 1024 (b*16+m), 128 threads (thread d: h=d>>4, t=d&15)
// ---------------------------------------------------------------------------
__global__ __launch_bounds__(128) void reduce_kernel(const float* __restrict__ W_out) {
  const int bm = blockIdx.x;
  const int b = bm >> 4;
  const int m = bm & 15;
  const int d = threadIdx.x;
  const int h = d >> 4;
  const int t = d & 15;
  __shared__ float heads[DD];
  float M = -1e30f, S = 0.f, A = 0.f;
#pragma unroll
  for (int c = 0; c < NCHUNK; c++) {
    const int idx = ((b * NCHUNK + c) * HH + h) * BEAM + m;
    float mc = g_pm[idx];
    float sc = g_ps[idx];
    float ac = g_pacc[idx * DHH + t];
    float mn = fmaxf(M, mc);
    float e1 = __expf(M - mn);
    float e2 = __expf(mc - mn);
    S = S * e1 + sc * e2;
    A = A * e1 + ac * e2;
    M = mn;
  }
  heads[d] = A / S;
  __syncthreads();
  float a = 0.f;
#pragma unroll 8
  for (int k = 0; k < DD; k++) a = fmaf(heads[k], W_out[k * DD + d], a);
  g_glim[bm * DD + d] = a;
}

// ---------------------------------------------------------------------------
// K6: beam-batched logits: out_raw[(b,m),n] = masked tanh-clipped glim·lk
// grid (64, 8), 256 threads (thread = local node)
// ---------------------------------------------------------------------------
__global__ __launch_bounds__(256) void logits_kernel(float* __restrict__ out) {
  const int b = blockIdx.x, c = blockIdx.y;
  const int tid = threadIdx.x;
  __shared__ float glim_s[BEAM][DD];         // 8 KB
  __shared__ unsigned char mk[BEAM][260];
  for (int i = tid; i < BEAM * DD; i += 256) glim_s[i >> 7][i & 127] = g_glim[b * BEAM * DD + i];
  for (int i = tid; i < BEAM * 256; i += 256) {
    int m = i >> 8, n = i & 255;
    mk[m][n] = (n < CHN) ? g_mask[((size_t)(b * BEAM + m)) * NN + c * CHN + n] : (unsigned char)1;
  }
  __syncthreads();
  if (tid >= CHN) return;
  const int n = c * CHN + tid;
  const float* __restrict__ lk = g_kt + ((size_t)b * 384 + 256) * NN + n;
  float s[BEAM];
#pragma unroll
  for (int m = 0; m < BEAM; m++) s[m] = 0.f;
#pragma unroll 4
  for (int f = 0; f < DD; f += 4) {
    float l0 = lk[(size_t)(f + 0) * NN];
    float l1 = lk[(size_t)(f + 1) * NN];
    float l2 = lk[(size_t)(f + 2) * NN];
    float l3 = lk[(size_t)(f + 3) * NN];
#pragma unroll
    for (int m = 0; m < BEAM; m++) {
      float4 g4 = *(const float4*)&glim_s[m][f];
      s[m] = fmaf(g4.x, l0, s[m]);
      s[m] = fmaf(g4.y, l1, s[m]);
      s[m] = fmaf(g4.z, l2, s[m]);
      s[m] = fmaf(g4.w, l3, s[m]);
    }
  }
  const float invsq = 0.08838834764831845f;  // 1/sqrt(128)
#pragma unroll
  for (int m = 0; m < BEAM; m++) {
    float v = 10.f * tanhf(s[m] * invsq);
    if (mk[m][tid]) v = -FLT_MAX;
    out[((size_t)(b * BEAM + m)) * NN + n] = v;
  }
}

// ---------------------------------------------------------------------------
// K7: finalize per (b,m): log_softmax over raw logits in-place + top3
// grid 1024, 256 threads
// ---------------------------------------------------------------------------
__global__ __launch_bounds__(256) void finalize_kernel(float* __restrict__ out) {
  const int bm = blockIdx.x;
  const int tid = threadIdx.x;
  float* __restrict__ lp = out + (size_t)bm * NN;
  __shared__ float logits[NN];
  __shared__ float red[256];
  __shared__ float stv[256][3];
  __shared__ int sti[256][3];

  float tv0 = -INFINITY, tv1 = -INFINITY, tv2 = -INFINITY;
  int ti0 = 0, ti1 = 0, ti2 = 0;
  float lmax = -INFINITY;
#pragma unroll 1
  for (int k = 0; k < 8; k++) {
    const int n = tid + 256 * k;
    if (n >= NN) break;
    float v = lp[n];
    logits[n] = v;
    lmax = fmaxf(lmax, v);
    if (v > tv0) { tv2 = tv1; ti2 = ti1; tv1 = tv0; ti1 = ti0; tv0 = v; ti0 = n; }
    else if (v > tv1) { tv2 = tv1; ti2 = ti1; tv1 = v; ti1 = n; }
    else if (v > tv2) { tv2 = v; ti2 = n; }
  }
  stv[tid][0] = tv0; stv[tid][1] = tv1; stv[tid][2] = tv2;
  sti[tid][0] = ti0; sti[tid][1] = ti1; sti[tid][2] = ti2;
  red[tid] = lmax;
  __syncthreads();
  for (int s2 = 128; s2 > 0; s2 >>= 1) {
    if (tid < s2) red[tid] = fmaxf(red[tid], red[tid + s2]);
    __syncthreads();
  }
  lmax = red[0];
  __syncthreads();
  float lsum = 0.f;
  for (int n = tid; n < NN; n += 256) lsum += fexp(logits[n] - lmax);
  red[tid] = lsum;
  __syncthreads();
  for (int s2 = 128; s2 > 0; s2 >>= 1) {
    if (tid < s2) red[tid] += red[tid + s2];
    __syncthreads();
  }
  const float lse = lmax + __logf(red[0]);

  for (int n = tid; n < NN; n += 256) lp[n] = logits[n] - lse;

  for (int s2 = 128; s2 > 0; s2 >>= 1) {
    if (tid < s2) {
      float a0 = stv[tid][0], a1 = stv[tid][1], a2 = stv[tid][2];
      int i0 = sti[tid][0], i1 = sti[tid][1], i2 = sti[tid][2];
#pragma unroll
      for (int j = 0; j < 3; j++) {
        float v = stv[tid + s2][j];
        int ii = sti[tid + s2][j];
        if (v > a0) { a2 = a1; i2 = i1; a1 = a0; i1 = i0; a0 = v; i0 = ii; }
        else if (v > a1) { a2 = a1; i2 = i1; a1 = v; i1 = ii; }
        else if (v > a2) { a2 = v; i2 = ii; }
      }
      stv[tid][0] = a0; stv[tid][1] = a1; stv[tid][2] = a2;
      sti[tid][0] = i0; sti[tid][1] = i1; sti[tid][2] = i2;
    }
    __syncthreads();
  }
  if (tid == 0) {
    float* tvo = out + (size_t)BB * BEAM * NN + bm * 3;
    float* tio = out + (size_t)BB * BEAM * NN + (size_t)BB * BEAM * 3 + bm * 3;
    tvo[0] = stv[0][0] - lse; tvo[1] = stv[0][1] - lse; tvo[2] = stv[0][2] - lse;
    tio[0] = (float)sti[0][0]; tio[1] = (float)sti[0][1]; tio[2] = (float)sti[0][2];
  }
}

// ---------------------------------------------------------------------------
extern "C" void kernel_launch(void* const* d_in, const int* in_sizes, int n_in,
                              void* d_out, int out_size) {
  const float* emb = nullptr;
  const float* W_node = nullptr;
  const float* W_fixed = nullptr;
  const float* W_step = nullptr;
  const float* W_out = nullptr;
  const int* seq = nullptr;
  const unsigned char* mask = nullptr;
  for (int i = 0; i < n_in; i++) {
    int sz = in_sizes[i];
    if (sz == BB * NN * DD) emb = (const float*)d_in[i];
    else if (sz == DD * 3 * DD) W_node = (const float*)d_in[i];
    else if (sz == 2 * DD * DD) W_step = (const float*)d_in[i];
    else if (sz == BB * BEAM * 2) seq = (const int*)d_in[i];
    else if (sz == BB * BEAM * NN) mask = (const unsigned char*)d_in[i];
    else if (sz == DD * DD) {
      if (!W_fixed) W_fixed = (const float*)d_in[i];
      else W_out = (const float*)d_in[i];
    }
  }
  float* out = (float*)d_out;

  zero_isbool_kernel<<<1, 1>>>();
  detect_mask_kernel<<<64, 256>>>(mask);
  convert_mask_kernel<<<(BB * BEAM * NN + 255) / 256, 256>>>(mask);
  fpart_kernel<<<dim3(BB, NCHUNK), 128>>>(emb);
  kvl_gemm<<<dim3(3, (BB * NN) / 128), 256>>>(emb, W_node);
  query_kernel<<<BB * BEAM, 128>>>(emb, W_fixed, W_step, seq);
  glimpse_kernel<<<dim3(BB, NCHUNK), 256>>>();
  reduce_kernel<<<BB * BEAM, 128>>>(W_out);
  logits_kernel<<<dim3(BB, NCHUNK), 256>>>(out);
  finalize_kernel<<<BB * BEAM, 256>>>(out);
}